// round 2
// baseline (speedup 1.0000x reference)
#include <cuda_runtime.h>

#define NB 64
#define NP 24564
#define NM 16
#define NC 21
#define BLK 256
#define RPT 8
#define CH (BLK * RPT)                 // 2048 priors per block
#define GX ((NP + CH - 1) / CH)        // 12
#define SBLK 1024
#define NPT ((NP + SBLK - 1) / SBLK)   // 24

// -------- scratch (no allocations allowed) --------
__device__ float g_mined[(size_t)NB * NP];           // mined loss_c (0 for positives)
__device__ unsigned short g_packed[(size_t)NB * NP]; // conf(5b) | bt_idx(4b)<<5 | pos<<9
__device__ unsigned long long g_bpkey[NB * NM];      // per-truth best prior key
__device__ int g_numpos[NB];
__device__ float g_sumpos[NB];                       // sum of loss_c_all over positives
__device__ float g_lossl;
__device__ float g_lossc;

__device__ __forceinline__ float sl1_sum(float tx1, float ty1, float tx2, float ty2,
                                         float px, float py, float pw, float ph,
                                         float4 ld)
{
    float lt0 = ((tx1 + tx2) * 0.5f - px) / (0.1f * pw);
    float lt1 = ((ty1 + ty2) * 0.5f - py) / (0.1f * ph);
    float lt2 = __logf((tx2 - tx1) / pw) / 0.2f;
    float lt3 = __logf((ty2 - ty1) / ph) / 0.2f;
    float s = 0.f, d, a;
    d = ld.x - lt0; a = fabsf(d); s += (a < 1.f) ? 0.5f * d * d : a - 0.5f;
    d = ld.y - lt1; a = fabsf(d); s += (a < 1.f) ? 0.5f * d * d : a - 0.5f;
    d = ld.z - lt2; a = fabsf(d); s += (a < 1.f) ? 0.5f * d * d : a - 0.5f;
    d = ld.w - lt3; a = fabsf(d); s += (a < 1.f) ? 0.5f * d * d : a - 0.5f;
    return s;
}

__global__ void k_init()
{
    int t = threadIdx.x;
    if (t < NB * NM) g_bpkey[t] = 0ull;
    if (t < NB) { g_numpos[t] = 0; g_sumpos[t] = 0.f; }
    if (t == 0) { g_lossl = 0.f; g_lossc = 0.f; }
}

__global__ void __launch_bounds__(BLK) k_match(const float* __restrict__ loc,
                                               const float* __restrict__ conf,
                                               const float* __restrict__ priors,
                                               const float* __restrict__ targets)
{
    int b = blockIdx.y;
    __shared__ float s_conf[BLK * NC];     // 21504 B, staged conf rows
    __shared__ float s_t[NM][6];           // x1,y1,x2,y2,area,label
    __shared__ unsigned long long s_key[NM];
    __shared__ float s_lossl, s_sumpos;
    __shared__ int s_np;
    int tid = threadIdx.x;

    if (tid < NM) {
        const float* tg = targets + ((size_t)b * NM + tid) * 5;
        float x1 = tg[0], y1 = tg[1], x2 = tg[2], y2 = tg[3];
        s_t[tid][0] = x1; s_t[tid][1] = y1; s_t[tid][2] = x2; s_t[tid][3] = y2;
        s_t[tid][4] = (x2 - x1) * (y2 - y1);
        s_t[tid][5] = tg[4];
        s_key[tid] = 0ull;
    }
    if (tid == 0) { s_lossl = 0.f; s_sumpos = 0.f; s_np = 0; }

    float lov[NM];
    int lpi[NM];
#pragma unroll
    for (int j = 0; j < NM; j++) { lov[j] = -1.f; lpi[j] = 0; }

    float t_lossl = 0.f, t_sumpos = 0.f;
    int t_np = 0;
    int blockStart = blockIdx.x * CH;

    for (int r = 0; r < RPT; r++) {
        int p0 = blockStart + r * BLK;
        __syncthreads();  // previous round's smem reads done (also covers s_t init)
        // stage conf rows [p0, p0+256) coalesced
        {
            int rows = NP - p0;
            if (rows > BLK) rows = BLK;
            int lim = rows * NC;
            const float* src = conf + ((size_t)b * NP + p0) * NC;
            for (int i = tid; i < lim; i += BLK) s_conf[i] = src[i];
        }
        __syncthreads();

        int p = p0 + tid;
        if (p < NP) {
            float4 pr = __ldg((const float4*)priors + p);
            float bx1 = pr.x - pr.z * 0.5f;
            float by1 = pr.y - pr.w * 0.5f;
            float bx2 = pr.x + pr.z * 0.5f;
            float by2 = pr.y + pr.w * 0.5f;
            float area_b = (bx2 - bx1) * (by2 - by1);

            float bov = -1.f;
            int bj = 0;
#pragma unroll
            for (int j = 0; j < NM; j++) {
                float ix1 = fmaxf(s_t[j][0], bx1);
                float iy1 = fmaxf(s_t[j][1], by1);
                float ix2 = fminf(s_t[j][2], bx2);
                float iy2 = fminf(s_t[j][3], by2);
                float iw = fmaxf(ix2 - ix1, 0.f);
                float ih = fmaxf(iy2 - iy1, 0.f);
                float inter = iw * ih;
                float iou = __fdividef(inter, s_t[j][4] + area_b - inter);
                if (iou > bov) { bov = iou; bj = j; }          // first-max over j
                if (iou > lov[j]) { lov[j] = iou; lpi[j] = p; } // first-max over p
            }

            // logsumexp (no max-shift: inputs ~N(0,1), no overflow possible)
            const float* row = s_conf + tid * NC;
            float es = 0.f;
#pragma unroll
            for (int c = 0; c < NC; c++) es += __expf(row[c]);
            float lse = __logf(es);

            int cf = 0;
            bool pos = false;
            if (!(bov < 0.5f)) { cf = (int)(s_t[bj][5] + 1.0f); pos = true; }
            float lca = lse - row[cf];

            size_t off = (size_t)b * NP + p;
            if (pos) {
                float4 ld = __ldg((const float4*)loc + off);
                t_lossl += sl1_sum(s_t[bj][0], s_t[bj][1], s_t[bj][2], s_t[bj][3],
                                   pr.x, pr.y, pr.z, pr.w, ld);
                t_sumpos += lca;
                t_np++;
                g_mined[off] = 0.f;
            } else {
                g_mined[off] = lca;
            }
            g_packed[off] = (unsigned short)(cf | (bj << 5) | ((pos ? 1 : 0) << 9));
        }
    }

#pragma unroll
    for (int j = 0; j < NM; j++) {
        if (lov[j] >= 0.f) {
            unsigned long long key =
                ((unsigned long long)__float_as_uint(lov[j]) << 32) |
                (unsigned long long)(0xFFFFFFFFu - (unsigned)lpi[j]);
            atomicMax(&s_key[j], key);
        }
    }
    atomicAdd(&s_lossl, t_lossl);
    atomicAdd(&s_sumpos, t_sumpos);
    atomicAdd(&s_np, t_np);
    __syncthreads();

    if (tid < NM && s_key[tid]) atomicMax(&g_bpkey[b * NM + tid], s_key[tid]);
    if (tid == 0) {
        atomicAdd(&g_lossl, s_lossl);
        atomicAdd(&g_sumpos[b], s_sumpos);
        atomicAdd(&g_numpos[b], s_np);
    }
}

// Sequential per-batch override fixup (last-write-wins on duplicate best-prior indices)
__global__ void k_fix(const float* __restrict__ loc,
                      const float* __restrict__ conf,
                      const float* __restrict__ priors,
                      const float* __restrict__ targets)
{
    int b = threadIdx.x;
    if (b >= NB) return;
    float d_lossl = 0.f;
    for (int j = 0; j < NM; j++) {
        unsigned long long key = g_bpkey[b * NM + j];
        int p = (int)(0xFFFFFFFFu - (unsigned)(key & 0xFFFFFFFFull));
        size_t off = (size_t)b * NP + p;
        const float* cr = conf + off * NC;
        float es = 0.f;
        for (int c = 0; c < NC; c++) es += __expf(cr[c]);
        float lse = __logf(es);

        unsigned us = g_packed[off];
        int cold = us & 31;
        int btold = (us >> 5) & 15;
        bool posold = (us >> 9) & 1;

        const float* tgj = targets + ((size_t)b * NM + j) * 5;
        int cnew = (int)(tgj[4] + 1.0f);
        float lca_new = lse - cr[cnew];
        float4 pr = __ldg((const float4*)priors + p);
        float4 ld = __ldg((const float4*)loc + off);
        float sl_new = sl1_sum(tgj[0], tgj[1], tgj[2], tgj[3],
                               pr.x, pr.y, pr.z, pr.w, ld);
        if (posold) {
            float lca_old = lse - cr[cold];
            const float* tgo = targets + ((size_t)b * NM + btold) * 5;
            float sl_old = sl1_sum(tgo[0], tgo[1], tgo[2], tgo[3],
                                   pr.x, pr.y, pr.z, pr.w, ld);
            g_sumpos[b] += lca_new - lca_old;
            d_lossl += sl_new - sl_old;
        } else {
            g_numpos[b] += 1;
            g_sumpos[b] += lca_new;
            d_lossl += sl_new;
            g_mined[off] = 0.f;
        }
        g_packed[off] = (unsigned short)(cnew | (j << 5) | (1 << 9));
    }
    atomicAdd(&g_lossl, d_lossl);
}

// Register-resident per-batch radix select of the K-th largest mined value.
// sum(selected) = sum(v > t*) + (K - count_gt) * t*   (tie-exact)
__global__ void __launch_bounds__(SBLK) k_select()
{
    int b = blockIdx.x;
    __shared__ unsigned hist[32][256];   // per-warp histograms, 32 KB
    __shared__ unsigned s_prefix, s_krem;
    __shared__ float s_sum;
    __shared__ unsigned s_cgt;
    int tid = threadIdx.x;
    int wid = tid >> 5;

    int np = g_numpos[b];
    long long Kl = 3ll * np;
    int K = (Kl < (long long)(NP - 1)) ? (int)Kl : (NP - 1);
    if (K <= 0) {
        if (tid == 0) atomicAdd(&g_lossc, g_sumpos[b]);
        return;
    }

    // load whole batch into registers (pad with 0.0f — mined values are >= 0,
    // padding only matters when threshold hits 0, where its contribution is 0)
    unsigned v[NPT];
    const float* mb = g_mined + (size_t)b * NP;
#pragma unroll
    for (int k = 0; k < NPT; k++) {
        int i = tid + k * SBLK;
        v[k] = (i < NP) ? __float_as_uint(mb[i]) : 0u;
    }

    if (tid == 0) { s_prefix = 0u; s_krem = (unsigned)K; s_sum = 0.f; s_cgt = 0u; }

    for (int pass = 0; pass < 4; pass++) {
        int shift = 24 - 8 * pass;
        for (int i = tid; i < 32 * 256; i += SBLK) ((unsigned*)hist)[i] = 0;
        __syncthreads();
        unsigned pref = s_prefix;
        unsigned hi = (pref >> shift) >> 8;   // two shifts: avoids UB at shift=24
#pragma unroll
        for (int k = 0; k < NPT; k++) {
            unsigned u = v[k];
            if (((u >> shift) >> 8) == hi)
                atomicAdd(&hist[wid][(u >> shift) & 255u], 1u);
        }
        __syncthreads();
        if (tid < 256) {
            unsigned s = 0;
#pragma unroll
            for (int w = 0; w < 32; w++) s += hist[w][tid];
            hist[0][tid] = s;
        }
        __syncthreads();
        if (tid == 0) {
            unsigned kr = s_krem;
            int d = 255;
            while (hist[0][d] < kr) { kr -= hist[0][d]; d--; }
            s_prefix = pref | ((unsigned)d << shift);
            s_krem = kr;
        }
        __syncthreads();
    }

    unsigned tb = s_prefix;
    float lsum = 0.f;
    unsigned lcnt = 0;
#pragma unroll
    for (int k = 0; k < NPT; k++) {
        if (v[k] > tb) { lsum += __uint_as_float(v[k]); lcnt++; }
    }
#pragma unroll
    for (int o = 16; o > 0; o >>= 1) {
        lsum += __shfl_down_sync(0xFFFFFFFFu, lsum, o);
        lcnt += __shfl_down_sync(0xFFFFFFFFu, lcnt, o);
    }
    if ((tid & 31) == 0) { atomicAdd(&s_sum, lsum); atomicAdd(&s_cgt, lcnt); }
    __syncthreads();
    if (tid == 0) {
        float lossc_b = g_sumpos[b] + s_sum + (float)(K - (int)s_cgt) * __uint_as_float(tb);
        atomicAdd(&g_lossc, lossc_b);
    }
}

__global__ void k_final(float* out)
{
    int n = 0;
    for (int b = 0; b < NB; b++) n += g_numpos[b];
    float fn = (float)n;
    out[0] = g_lossl / fn;
    out[1] = g_lossc / fn;
}

extern "C" void kernel_launch(void* const* d_in, const int* in_sizes, int n_in,
                              void* d_out, int out_size)
{
    const float* loc = (const float*)d_in[0];
    const float* conf = (const float*)d_in[1];
    const float* priors = (const float*)d_in[2];
    const float* targets = (const float*)d_in[3];

    k_init<<<1, 1024>>>();
    dim3 g(GX, NB);
    k_match<<<g, BLK>>>(loc, conf, priors, targets);
    k_fix<<<1, NB>>>(loc, conf, priors, targets);
    k_select<<<NB, SBLK>>>();
    k_final<<<1, 1>>>((float*)d_out);
}

// round 4
// speedup vs baseline: 1.2682x; 1.2682x over previous
#include <cuda_runtime.h>

#define NB 64
#define NP 24564
#define NM 16
#define NC 21
#define WPB 8                           // warps per block
#define PRW 32                          // priors per warp per round
#define RNDS 8
#define CH (WPB * PRW * RNDS)           // 2048 priors per block
#define GX ((NP + CH - 1) / CH)         // 12
#define SBLK 1024
#define NF4 ((NP * NC) / 4)             // floats per (b) conf block / 4 (exact: 515844/4)

// -------- scratch (no allocations allowed) --------
__device__ float g_mined[(size_t)NB * NP];           // mined loss_c (0 for positives)
__device__ unsigned short g_packed[(size_t)NB * NP]; // conf(5b) | bt_idx(4b)<<5 | pos<<9
__device__ unsigned long long g_bpkey[NB * NM];      // per-truth best prior key
__device__ int g_numpos[NB];
__device__ float g_sumpos[NB];                       // sum of loss_c_all over positives
__device__ float g_lossl;
__device__ float g_lossc;

__device__ __forceinline__ float sl1_sum(float tx1, float ty1, float tx2, float ty2,
                                         float px, float py, float pw, float ph,
                                         float4 ld)
{
    float lt0 = ((tx1 + tx2) * 0.5f - px) / (0.1f * pw);
    float lt1 = ((ty1 + ty2) * 0.5f - py) / (0.1f * ph);
    float lt2 = __logf((tx2 - tx1) / pw) / 0.2f;
    float lt3 = __logf((ty2 - ty1) / ph) / 0.2f;
    float s = 0.f, d, a;
    d = ld.x - lt0; a = fabsf(d); s += (a < 1.f) ? 0.5f * d * d : a - 0.5f;
    d = ld.y - lt1; a = fabsf(d); s += (a < 1.f) ? 0.5f * d * d : a - 0.5f;
    d = ld.z - lt2; a = fabsf(d); s += (a < 1.f) ? 0.5f * d * d : a - 0.5f;
    d = ld.w - lt3; a = fabsf(d); s += (a < 1.f) ? 0.5f * d * d : a - 0.5f;
    return s;
}

__global__ void k_init()
{
    int t = threadIdx.x;
    if (t < NB * NM) g_bpkey[t] = 0ull;
    if (t < NB) { g_numpos[t] = 0; g_sumpos[t] = 0.f; }
    if (t == 0) { g_lossl = 0.f; g_lossc = 0.f; }
}

__global__ void __launch_bounds__(WPB * 32) k_match(const float* __restrict__ loc,
                                                    const float* __restrict__ conf,
                                                    const float* __restrict__ priors,
                                                    const float* __restrict__ targets)
{
    int b = blockIdx.y;
    __shared__ float s_conf[WPB][2][PRW * NC];   // 43008 B, warp-private double buffers
    __shared__ float s_t[NM][6];
    __shared__ unsigned long long s_key[NM];
    __shared__ float s_lossl, s_sumpos;
    __shared__ int s_np;

    int tid = threadIdx.x;
    int w = tid >> 5, lane = tid & 31;

    if (tid < NM) {
        const float* tg = targets + ((size_t)b * NM + tid) * 5;
        float x1 = tg[0], y1 = tg[1], x2 = tg[2], y2 = tg[3];
        s_t[tid][0] = x1; s_t[tid][1] = y1; s_t[tid][2] = x2; s_t[tid][3] = y2;
        s_t[tid][4] = (x2 - x1) * (y2 - y1);
        s_t[tid][5] = tg[4];
        s_key[tid] = 0ull;
    }
    if (tid == 0) { s_lossl = 0.f; s_sumpos = 0.f; s_np = 0; }
    __syncthreads();

    float lov[NM];
    int lpi[NM];
#pragma unroll
    for (int j = 0; j < NM; j++) { lov[j] = -1.f; lpi[j] = 0; }

    float t_lossl = 0.f, t_sumpos = 0.f;
    int t_np = 0;

    const float4* conf4 = (const float4*)conf;
    size_t cb4 = ((size_t)b * NP * NC) >> 2;     // exact: NP*NC divisible by 4
    int warpStart = blockIdx.x * CH + w * PRW;

    float4 pre[6];
    {
        int p0 = warpStart;
        int rows = NP - p0; if (rows > PRW) rows = PRW;
        int n4 = (rows > 0) ? (rows * NC) >> 2 : 0;   // rows*NC % 4 == 0 for rows in {32,20}
        size_t base4 = cb4 + (((size_t)p0 * NC) >> 2);
#pragma unroll
        for (int k = 0; k < 6; k++) {
            int i = lane + 32 * k;
            pre[k] = (i < n4) ? __ldg(conf4 + base4 + i) : make_float4(0.f, 0.f, 0.f, 0.f);
        }
    }

    for (int r = 0; r < RNDS; r++) {
        int p0 = warpStart + r * (WPB * PRW);
        int rows = NP - p0; if (rows > PRW) rows = PRW;
        float* buf = &s_conf[w][r & 1][0];

        if (rows > 0) {
            float4* b4 = (float4*)buf;
#pragma unroll
            for (int k = 0; k < 5; k++) b4[lane + 32 * k] = pre[k];
            if (lane < 8) b4[lane + 160] = pre[5];
        }

        if (r + 1 < RNDS) {
            int p1 = warpStart + (r + 1) * (WPB * PRW);
            int rows1 = NP - p1; if (rows1 > PRW) rows1 = PRW;
            int n4 = (rows1 > 0) ? (rows1 * NC) >> 2 : 0;
            size_t base4 = cb4 + (((size_t)p1 * NC) >> 2);
#pragma unroll
            for (int k = 0; k < 6; k++) {
                int i = lane + 32 * k;
                pre[k] = (i < n4) ? __ldg(conf4 + base4 + i) : make_float4(0.f, 0.f, 0.f, 0.f);
            }
        }
        __syncwarp();

        if (lane < rows) {
            int p = p0 + lane;
            float4 pr = __ldg((const float4*)priors + p);
            float bx1 = pr.x - pr.z * 0.5f;
            float by1 = pr.y - pr.w * 0.5f;
            float bx2 = pr.x + pr.z * 0.5f;
            float by2 = pr.y + pr.w * 0.5f;
            float area_b = (bx2 - bx1) * (by2 - by1);

            float bov = -1.f;
            int bj = 0;
#pragma unroll
            for (int j = 0; j < NM; j++) {
                float ix1 = fmaxf(s_t[j][0], bx1);
                float iy1 = fmaxf(s_t[j][1], by1);
                float ix2 = fminf(s_t[j][2], bx2);
                float iy2 = fminf(s_t[j][3], by2);
                float iw = fmaxf(ix2 - ix1, 0.f);
                float ih = fmaxf(iy2 - iy1, 0.f);
                float inter = iw * ih;
                float iou = __fdividef(inter, s_t[j][4] + area_b - inter);
                if (iou > bov) { bov = iou; bj = j; }          // first-max over j
                if (iou > lov[j]) { lov[j] = iou; lpi[j] = p; } // first-max over p
            }

            int cf = 0;
            bool pos = false;
            if (!(bov < 0.5f)) { cf = (int)(s_t[bj][5] + 1.0f); pos = true; }

            // logsumexp + gather in one smem pass (no max-shift: inputs ~N(0,1))
            const float* row = buf + lane * NC;
            float es = 0.f, gath = 0.f;
#pragma unroll
            for (int c = 0; c < NC; c++) {
                float x = row[c];
                es += __expf(x);
                if (c == cf) gath = x;
            }
            float lca = __logf(es) - gath;

            size_t off = (size_t)b * NP + p;
            if (pos) {
                float4 ld = __ldg((const float4*)loc + off);
                t_lossl += sl1_sum(s_t[bj][0], s_t[bj][1], s_t[bj][2], s_t[bj][3],
                                   pr.x, pr.y, pr.z, pr.w, ld);
                t_sumpos += lca;
                t_np++;
                g_mined[off] = 0.f;
            } else {
                g_mined[off] = lca;
            }
            g_packed[off] = (unsigned short)(cf | (bj << 5) | ((pos ? 1 : 0) << 9));
        }
        __syncwarp();
    }

#pragma unroll
    for (int j = 0; j < NM; j++) {
        if (lov[j] >= 0.f) {
            unsigned long long key =
                ((unsigned long long)__float_as_uint(lov[j]) << 32) |
                (unsigned long long)(0xFFFFFFFFu - (unsigned)lpi[j]);
            atomicMax(&s_key[j], key);
        }
    }
    atomicAdd(&s_lossl, t_lossl);
    atomicAdd(&s_sumpos, t_sumpos);
    atomicAdd(&s_np, t_np);
    __syncthreads();

    if (tid < NM && s_key[tid]) atomicMax(&g_bpkey[b * NM + tid], s_key[tid]);
    if (tid == 0) {
        atomicAdd(&g_lossl, s_lossl);
        atomicAdd(&g_sumpos[b], s_sumpos);
        atomicAdd(&g_numpos[b], s_np);
    }
}

// Sequential per-batch override fixup (last-write-wins on duplicate best-prior indices)
__global__ void k_fix(const float* __restrict__ loc,
                      const float* __restrict__ conf,
                      const float* __restrict__ priors,
                      const float* __restrict__ targets)
{
    int b = threadIdx.x;
    if (b >= NB) return;
    float d_lossl = 0.f;
    for (int j = 0; j < NM; j++) {
        unsigned long long key = g_bpkey[b * NM + j];
        int p = (int)(0xFFFFFFFFu - (unsigned)(key & 0xFFFFFFFFull));
        size_t off = (size_t)b * NP + p;
        const float* cr = conf + off * NC;
        float es = 0.f;
        for (int c = 0; c < NC; c++) es += __expf(cr[c]);
        float lse = __logf(es);

        unsigned us = g_packed[off];
        int cold = us & 31;
        int btold = (us >> 5) & 15;
        bool posold = (us >> 9) & 1;

        const float* tgj = targets + ((size_t)b * NM + j) * 5;
        int cnew = (int)(tgj[4] + 1.0f);
        float lca_new = lse - cr[cnew];
        float4 pr = __ldg((const float4*)priors + p);
        float4 ld = __ldg((const float4*)loc + off);
        float sl_new = sl1_sum(tgj[0], tgj[1], tgj[2], tgj[3],
                               pr.x, pr.y, pr.z, pr.w, ld);
        if (posold) {
            float lca_old = lse - cr[cold];
            const float* tgo = targets + ((size_t)b * NM + btold) * 5;
            float sl_old = sl1_sum(tgo[0], tgo[1], tgo[2], tgo[3],
                                   pr.x, pr.y, pr.z, pr.w, ld);
            g_sumpos[b] += lca_new - lca_old;
            d_lossl += sl_new - sl_old;
        } else {
            g_numpos[b] += 1;
            g_sumpos[b] += lca_new;
            d_lossl += sl_new;
            g_mined[off] = 0.f;
        }
        g_packed[off] = (unsigned short)(cnew | (j << 5) | (1 << 9));
    }
    atomicAdd(&g_lossl, d_lossl);
}

// Per-batch radix select of K-th largest; warp-aggregated histogram (match_any)
__global__ void __launch_bounds__(SBLK) k_select()
{
    int b = blockIdx.x;
    __shared__ unsigned hist[256];
    __shared__ unsigned s_prefix, s_krem;
    __shared__ float s_sum;
    __shared__ unsigned s_cgt;
    int tid = threadIdx.x;
    int lane = tid & 31;

    int np = g_numpos[b];
    long long Kl = 3ll * np;
    int K = (Kl < (long long)(NP - 1)) ? (int)Kl : (NP - 1);
    if (K <= 0) {
        if (tid == 0) atomicAdd(&g_lossc, g_sumpos[b]);
        return;
    }

    // vectorized load (order irrelevant for selection); pad with 0.0f
    const float4* mb4 = (const float4*)(g_mined + (size_t)b * NP);  // NP%4==0
    unsigned v[24];
#pragma unroll
    for (int k = 0; k < 6; k++) {
        int i = tid + k * SBLK;
        float4 f = (i < NP / 4) ? __ldg(mb4 + i) : make_float4(0.f, 0.f, 0.f, 0.f);
        v[4 * k + 0] = __float_as_uint(f.x);
        v[4 * k + 1] = __float_as_uint(f.y);
        v[4 * k + 2] = __float_as_uint(f.z);
        v[4 * k + 3] = __float_as_uint(f.w);
    }

    if (tid == 0) { s_prefix = 0u; s_krem = (unsigned)K; s_sum = 0.f; s_cgt = 0u; }

    for (int pass = 0; pass < 4; pass++) {
        int shift = 24 - 8 * pass;
        if (tid < 256) hist[tid] = 0;
        __syncthreads();
        unsigned pref = s_prefix;
        unsigned hi = (pref >> shift) >> 8;
#pragma unroll
        for (int k = 0; k < 24; k++) {
            unsigned u = v[k];
            bool act = (((u >> shift) >> 8) == hi);
            unsigned bin = (u >> shift) & 255u;
            unsigned key = act ? bin : 0xFFFFFFFFu;
            unsigned m = __match_any_sync(0xFFFFFFFFu, key);
            if (act && (unsigned)(__ffs(m) - 1) == (unsigned)lane)
                atomicAdd(&hist[bin], __popc(m));
        }
        __syncthreads();
        if (tid == 0) {
            unsigned kr = s_krem;
            int d = 255;
            while (hist[d] < kr) { kr -= hist[d]; d--; }
            s_prefix = pref | ((unsigned)d << shift);
            s_krem = kr;
        }
        __syncthreads();
    }

    unsigned tb = s_prefix;
    float lsum = 0.f;
    unsigned lcnt = 0;
#pragma unroll
    for (int k = 0; k < 24; k++) {
        if (v[k] > tb) { lsum += __uint_as_float(v[k]); lcnt++; }
    }
#pragma unroll
    for (int o = 16; o > 0; o >>= 1) {
        lsum += __shfl_down_sync(0xFFFFFFFFu, lsum, o);
        lcnt += __shfl_down_sync(0xFFFFFFFFu, lcnt, o);
    }
    if (lane == 0) { atomicAdd(&s_sum, lsum); atomicAdd(&s_cgt, lcnt); }
    __syncthreads();
    if (tid == 0) {
        float lossc_b = g_sumpos[b] + s_sum + (float)(K - (int)s_cgt) * __uint_as_float(tb);
        atomicAdd(&g_lossc, lossc_b);
    }
}

__global__ void k_final(float* out)
{
    int n = 0;
    for (int b = 0; b < NB; b++) n += g_numpos[b];
    float fn = (float)n;
    out[0] = g_lossl / fn;
    out[1] = g_lossc / fn;
}

extern "C" void kernel_launch(void* const* d_in, const int* in_sizes, int n_in,
                              void* d_out, int out_size)
{
    const float* loc = (const float*)d_in[0];
    const float* conf = (const float*)d_in[1];
    const float* priors = (const float*)d_in[2];
    const float* targets = (const float*)d_in[3];

    k_init<<<1, 1024>>>();
    dim3 g(GX, NB);
    k_match<<<g, WPB * 32>>>(loc, conf, priors, targets);
    k_fix<<<1, NB>>>(loc, conf, priors, targets);
    k_select<<<NB, SBLK>>>();
    k_final<<<1, 1>>>((float*)d_out);
}